// round 1
// baseline (speedup 1.0000x reference)
#include <cuda_runtime.h>
#include <math.h>

// GPT-2 small config
#define BSZ   2
#define TSEQ  1024
#define CDIM  768
#define FFDIM 3072
#define NHEAD 12
#define NLAYER 12
#define DHEAD 64
#define VOCAB 50257
#define NROW  (BSZ * TSEQ)   // 2048

// ---------------------------------------------------------------------------
// Scratch (device globals — no allocation allowed)
// ---------------------------------------------------------------------------
__device__ float g_x  [NROW * CDIM];          // residual stream
__device__ float g_h  [NROW * CDIM];          // LN output
__device__ float g_qkv[NROW * 3 * CDIM];      // qkv projection
__device__ float g_att[NROW * CDIM];          // attention output
__device__ float g_ffn[NROW * FFDIM];         // FFN intermediate

// ---------------------------------------------------------------------------
// Embedding: x[n,c] = tok_embed[tokens[n],c] + pos_embed[n%T, c]
// ---------------------------------------------------------------------------
__global__ void embed_kernel(const int* __restrict__ tokens,
                             const float* __restrict__ tok,
                             const float* __restrict__ pos,
                             float* __restrict__ x) {
    int n = blockIdx.x;
    int t = n % TSEQ;
    int tk = tokens[n];
    const float* tr = tok + (size_t)tk * CDIM;
    const float* pr = pos + (size_t)t * CDIM;
    float* xr = x + (size_t)n * CDIM;
    for (int c = threadIdx.x; c < CDIM; c += blockDim.x)
        xr[c] = tr[c] + pr[c];
}

// ---------------------------------------------------------------------------
// LayerNorm (block per row, 256 threads)
// ---------------------------------------------------------------------------
__global__ void ln_kernel(const float* __restrict__ x,
                          const float* __restrict__ w,
                          const float* __restrict__ b,
                          float* __restrict__ out) {
    int n = blockIdx.x;
    const float* xr = x + (size_t)n * CDIM;
    float s = 0.f, s2 = 0.f;
    for (int c = threadIdx.x; c < CDIM; c += blockDim.x) {
        float v = xr[c];
        s += v; s2 += v * v;
    }
    __shared__ float red[64];
    #pragma unroll
    for (int o = 16; o; o >>= 1) {
        s  += __shfl_xor_sync(~0u, s,  o);
        s2 += __shfl_xor_sync(~0u, s2, o);
    }
    int wid = threadIdx.x >> 5, lid = threadIdx.x & 31;
    if (lid == 0) { red[wid] = s; red[wid + 32] = s2; }
    __syncthreads();
    if (threadIdx.x == 0) {
        float ts = 0.f, ts2 = 0.f;
        int nw = blockDim.x >> 5;
        for (int i = 0; i < nw; i++) { ts += red[i]; ts2 += red[i + 32]; }
        float m = ts / CDIM;
        float var = ts2 / CDIM - m * m;
        red[0] = m;
        red[1] = rsqrtf(var + 1e-5f);
    }
    __syncthreads();
    float m = red[0], r = red[1];
    float* orow = out + (size_t)n * CDIM;
    for (int c = threadIdx.x; c < CDIM; c += blockDim.x)
        orow[c] = (xr[c] - m) * r * w[c] + b[c];
}

// ---------------------------------------------------------------------------
// Generic NT SGEMM:  C[n,m] = sum_k A[n,k] * W[m,k]  (+bias, +GELU, +residual)
// A: [N,K] row-major, W: [M,K] row-major. K must be a multiple of 16 (it is:
// 768 or 3072). N multiple of 128 (2048). M may be ragged (50257).
// 128x128 tile, BK=16, 256 threads, 8x8 per-thread microtile.
// ---------------------------------------------------------------------------
#define BM 128
#define BN 128
#define BK 16
#define TM 8
#define TN 8

__global__ __launch_bounds__(256, 1)
void gemm_nt_kernel(const float* __restrict__ A,
                    const float* __restrict__ W,
                    const float* __restrict__ bias,      // may be null
                    const float* __restrict__ res,       // may be null, [N,M]
                    float* __restrict__ C,
                    int N, int M, int K, int gelu) {
    __shared__ float As[BK][BM];
    __shared__ float Bs[BK][BN];

    int tid = threadIdx.x;
    int bm = blockIdx.y * BM;   // row base (N dim)
    int bn = blockIdx.x * BN;   // col base (M dim)
    int tx = tid & 15, ty = tid >> 4;

    float acc[TM][TN];
    #pragma unroll
    for (int i = 0; i < TM; i++)
        #pragma unroll
        for (int j = 0; j < TN; j++) acc[i][j] = 0.f;

    for (int k0 = 0; k0 < K; k0 += BK) {
        // Load A tile (128 x 16) = 512 float4, transposed into As[k][n]
        #pragma unroll
        for (int i = 0; i < 2; i++) {
            int f = tid + i * 256;
            int row = f >> 2;
            int c4  = (f & 3) * 4;
            float4 v = *(const float4*)(A + (size_t)(bm + row) * K + k0 + c4);
            As[c4 + 0][row] = v.x; As[c4 + 1][row] = v.y;
            As[c4 + 2][row] = v.z; As[c4 + 3][row] = v.w;
        }
        // Load W tile (128 x 16), guard ragged M
        #pragma unroll
        for (int i = 0; i < 2; i++) {
            int f = tid + i * 256;
            int row = f >> 2;
            int c4  = (f & 3) * 4;
            int m = bn + row;
            float4 v = make_float4(0.f, 0.f, 0.f, 0.f);
            if (m < M) v = *(const float4*)(W + (size_t)m * K + k0 + c4);
            Bs[c4 + 0][row] = v.x; Bs[c4 + 1][row] = v.y;
            Bs[c4 + 2][row] = v.z; Bs[c4 + 3][row] = v.w;
        }
        __syncthreads();

        #pragma unroll
        for (int kk = 0; kk < BK; kk++) {
            float a[TM], bb[TN];
            #pragma unroll
            for (int i = 0; i < TM; i++) a[i] = As[kk][ty * TM + i];
            #pragma unroll
            for (int j = 0; j < TN; j++) bb[j] = Bs[kk][tx * TN + j];
            #pragma unroll
            for (int i = 0; i < TM; i++)
                #pragma unroll
                for (int j = 0; j < TN; j++)
                    acc[i][j] += a[i] * bb[j];
        }
        __syncthreads();
    }

    // Epilogue
    #pragma unroll
    for (int i = 0; i < TM; i++) {
        int n = bm + ty * TM + i;
        #pragma unroll
        for (int j = 0; j < TN; j++) {
            int m = bn + tx * TN + j;
            if (m < M) {
                float v = acc[i][j];
                if (bias) v += bias[m];
                if (gelu) {
                    float u = v;
                    v = 0.5f * u * (1.f + tanhf(0.7978845608028654f *
                                                (u + 0.044715f * u * u * u)));
                }
                size_t idx = (size_t)n * M + m;
                if (res) v += res[idx];
                C[idx] = v;
            }
        }
    }
}

// ---------------------------------------------------------------------------
// Attention: block per (query row t, batch-head). 128 threads.
// scores[j] = q . k_j * 1/8 for j <= t, stable softmax, o = P @ V.
// qkv layout per row n: [ q(0..767) | k(768..1535) | v(1536..2303) ]
// ---------------------------------------------------------------------------
__global__ void attn_kernel(const float* __restrict__ qkv,
                            float* __restrict__ out) {
    int t  = blockIdx.x;
    int bh = blockIdx.y;
    int b  = bh / NHEAD, h = bh % NHEAD;
    int Lq = t + 1;
    int n  = b * TSEQ + t;

    __shared__ float qs[DHEAD];
    __shared__ float sc[TSEQ];
    __shared__ float red[4];
    __shared__ float obuf[2][DHEAD];

    int tid = threadIdx.x;
    const float* qp = qkv + (size_t)n * (3 * CDIM) + h * DHEAD;
    if (tid < DHEAD) qs[tid] = qp[tid];
    __syncthreads();

    // Pass 1: scores + local max
    float lmax = -1e30f;
    for (int j = tid; j < Lq; j += 128) {
        const float4* kp = (const float4*)(qkv + (size_t)(b * TSEQ + j) * (3 * CDIM)
                                           + CDIM + h * DHEAD);
        float s = 0.f;
        #pragma unroll
        for (int d4 = 0; d4 < DHEAD / 4; d4++) {
            float4 kv = kp[d4];
            int d = d4 * 4;
            s += qs[d] * kv.x + qs[d + 1] * kv.y + qs[d + 2] * kv.z + qs[d + 3] * kv.w;
        }
        s *= 0.125f;   // 1/sqrt(64)
        sc[j] = s;
        lmax = fmaxf(lmax, s);
    }
    #pragma unroll
    for (int o = 16; o; o >>= 1) lmax = fmaxf(lmax, __shfl_xor_sync(~0u, lmax, o));
    if ((tid & 31) == 0) red[tid >> 5] = lmax;
    __syncthreads();
    float mx = fmaxf(fmaxf(red[0], red[1]), fmaxf(red[2], red[3]));
    __syncthreads();   // everyone has mx before red is reused

    // Pass 2: exp + sum
    float lsum = 0.f;
    for (int j = tid; j < Lq; j += 128) {
        float p = expf(sc[j] - mx);
        sc[j] = p;
        lsum += p;
    }
    #pragma unroll
    for (int o = 16; o; o >>= 1) lsum += __shfl_xor_sync(~0u, lsum, o);
    if ((tid & 31) == 0) red[tid >> 5] = lsum;
    __syncthreads();
    float denom = red[0] + red[1] + red[2] + red[3];

    // Pass 3: o[d] = sum_j p_j * V[j,d]; split j over two halves of the block
    int d = tid & 63, half = tid >> 6;
    float oacc = 0.f;
    for (int j = half; j < Lq; j += 2) {
        const float* vp = qkv + (size_t)(b * TSEQ + j) * (3 * CDIM)
                          + 2 * CDIM + h * DHEAD;
        oacc += sc[j] * vp[d];
    }
    obuf[half][d] = oacc;
    __syncthreads();
    if (tid < DHEAD)
        out[(size_t)n * CDIM + h * DHEAD + tid] =
            (obuf[0][tid] + obuf[1][tid]) / denom;
}

// ---------------------------------------------------------------------------
// Launcher
// ---------------------------------------------------------------------------
extern "C" void kernel_launch(void* const* d_in, const int* in_sizes, int n_in,
                              void* d_out, int out_size) {
    const int*   tokens    = (const int*)  d_in[0];
    const float* tok_embed = (const float*)d_in[1];
    const float* pos_embed = (const float*)d_in[2];
    const float* ln1_w     = (const float*)d_in[3];
    const float* ln1_b     = (const float*)d_in[4];
    const float* qkv_w     = (const float*)d_in[5];
    const float* qkv_b     = (const float*)d_in[6];
    const float* proj_w    = (const float*)d_in[7];
    const float* proj_b    = (const float*)d_in[8];
    const float* ln2_w     = (const float*)d_in[9];
    const float* ln2_b     = (const float*)d_in[10];
    const float* fc_w      = (const float*)d_in[11];
    const float* fc_b      = (const float*)d_in[12];
    const float* fc2_w     = (const float*)d_in[13];
    const float* fc2_b     = (const float*)d_in[14];
    const float* lnf_w     = (const float*)d_in[15];
    const float* lnf_b     = (const float*)d_in[16];
    float* logits = (float*)d_out;

    float *x, *h, *qkv, *att, *ffn;
    cudaGetSymbolAddress((void**)&x,   g_x);
    cudaGetSymbolAddress((void**)&h,   g_h);
    cudaGetSymbolAddress((void**)&qkv, g_qkv);
    cudaGetSymbolAddress((void**)&att, g_att);
    cudaGetSymbolAddress((void**)&ffn, g_ffn);

    embed_kernel<<<NROW, 256>>>(tokens, tok_embed, pos_embed, x);

    const int NB = NROW / BM;   // 16 row-blocks
    for (int l = 0; l < NLAYER; l++) {
        const float* l1w = ln1_w  + (size_t)l * CDIM;
        const float* l1b = ln1_b  + (size_t)l * CDIM;
        const float* qw  = qkv_w  + (size_t)l * 3 * CDIM * CDIM;
        const float* qb  = qkv_b  + (size_t)l * 3 * CDIM;
        const float* pw  = proj_w + (size_t)l * CDIM * CDIM;
        const float* pb  = proj_b + (size_t)l * CDIM;
        const float* l2w = ln2_w  + (size_t)l * CDIM;
        const float* l2b = ln2_b  + (size_t)l * CDIM;
        const float* fw  = fc_w   + (size_t)l * FFDIM * CDIM;
        const float* fb  = fc_b   + (size_t)l * FFDIM;
        const float* f2w = fc2_w  + (size_t)l * CDIM * FFDIM;
        const float* f2b = fc2_b  + (size_t)l * CDIM;

        // LN1
        ln_kernel<<<NROW, 256>>>(x, l1w, l1b, h);
        // QKV: [2048,768] x [2304,768]^T
        gemm_nt_kernel<<<dim3(3 * CDIM / BN, NB), 256>>>(
            h, qw, qb, nullptr, qkv, NROW, 3 * CDIM, CDIM, 0);
        // Attention
        attn_kernel<<<dim3(TSEQ, BSZ * NHEAD), 128>>>(qkv, att);
        // Proj + residual (in-place into x)
        gemm_nt_kernel<<<dim3(CDIM / BN, NB), 256>>>(
            att, pw, pb, x, x, NROW, CDIM, CDIM, 0);
        // LN2
        ln_kernel<<<NROW, 256>>>(x, l2w, l2b, h);
        // FC + GELU
        gemm_nt_kernel<<<dim3(FFDIM / BN, NB), 256>>>(
            h, fw, fb, nullptr, ffn, NROW, FFDIM, CDIM, 1);
        // FC2 + residual (in-place into x)
        gemm_nt_kernel<<<dim3(CDIM / BN, NB), 256>>>(
            ffn, f2w, f2b, x, x, NROW, CDIM, FFDIM, 0);
    }

    // Final LN
    ln_kernel<<<NROW, 256>>>(x, lnf_w, lnf_b, h);
    // LM head: [2048,768] x [50257,768]^T  -> logits
    gemm_nt_kernel<<<dim3((VOCAB + BN - 1) / BN, NB), 256>>>(
        h, tok_embed, nullptr, nullptr, logits, NROW, VOCAB, CDIM, 0);
}